// round 12
// baseline (speedup 1.0000x reference)
#include <cuda_runtime.h>
#include <cuda_bf16.h>
#include <math.h>

// Problem constants
#define T_STEPS 16384
#define D_IN    257
#define H_DIM   512
#define G4H     2048   // 4*H
#define O_DIM   257
#define REC_CTAS 64    // recurrence CTAs; each owns 8 hidden units (32 gate rows)
#define NREP    8      // replicas of the h-exchange buffer (spread L2 slices)

// Scratch (static __device__ arrays — no allocation allowed)
__device__ float    g_xg[(size_t)T_STEPS * G4H];   // 128 MB: precomputed input gates + biases
__device__ float    g_hs[(size_t)T_STEPS * H_DIM]; // 32 MB: h per timestep
// Tagged h exchange: [replica][parity][unit] -> (step_tag<<32)|float_bits
__device__ unsigned long long g_hx[NREP * 2 * H_DIM];

// ---------------------------------------------------------------------------
// init: reset exchange tags each launch (tags are monotonic within a launch)
// ---------------------------------------------------------------------------
__global__ void init_kernel() {
    const int idx = blockIdx.x * 256 + threadIdx.x;
    const int n = NREP * 2 * H_DIM;
    for (int i = idx; i < n; i += gridDim.x * 256) g_hx[i] = 0ull;
}

// ---------------------------------------------------------------------------
// Kernel A: x_gates[T, 4H] = stft @ W_ih^T + (b_ih + b_hh)
// ---------------------------------------------------------------------------
__global__ void __launch_bounds__(256) xgate_gemm(
    const float* __restrict__ stft, const float* __restrict__ W_ih,
    const float* __restrict__ b_ih, const float* __restrict__ b_hh)
{
    __shared__ float s_sh[16 * 260];  // row stride 260 (mult of 4 for float4)
    const int tid = threadIdx.x;
    const int t0  = blockIdx.x * 16;

    for (int r = 0; r < 16; r++)
        for (int d = tid; d < D_IN; d += 256)
            s_sh[r * 260 + d] = stft[(size_t)(t0 + r) * D_IN + d];
    __syncthreads();

    for (int cg = 0; cg < 8; cg++) {
        const int c = cg * 256 + tid;                  // 0..2047
        const float* wrow = W_ih + (size_t)c * D_IN;
        float acc[16];
        #pragma unroll
        for (int r = 0; r < 16; r++) acc[r] = 0.f;

        for (int dd = 0; dd < 64; dd++) {              // 64*4 = 256 of 257
            const float w0 = __ldg(wrow + dd * 4 + 0);
            const float w1 = __ldg(wrow + dd * 4 + 1);
            const float w2 = __ldg(wrow + dd * 4 + 2);
            const float w3 = __ldg(wrow + dd * 4 + 3);
            #pragma unroll
            for (int r = 0; r < 16; r++) {
                const float4 s4 = *reinterpret_cast<const float4*>(&s_sh[r * 260 + dd * 4]);
                float a = acc[r];
                a = fmaf(w0, s4.x, a);
                a = fmaf(w1, s4.y, a);
                a = fmaf(w2, s4.z, a);
                a = fmaf(w3, s4.w, a);
                acc[r] = a;
            }
        }
        const float wl = __ldg(wrow + 256);            // remainder d = 256
        #pragma unroll
        for (int r = 0; r < 16; r++) acc[r] = fmaf(wl, s_sh[r * 260 + 256], acc[r]);

        const float bias = __ldg(b_ih + c) + __ldg(b_hh + c);
        #pragma unroll
        for (int r = 0; r < 16; r++)
            g_xg[(size_t)(t0 + r) * G4H + c] = acc[r] + bias;
    }
}

// ---------------------------------------------------------------------------
// Kernel B: LSTM recurrence, persistent 64 CTAs x 256 threads.
// CTA b owns units u0=8b..8b+7 (32 gate rows). Thread (warp w, lane l):
//   row = l (gate=l>>3, unit=l&7), k-segment = w (64 k-values, 16 float4 regs).
// Per step: dot -> red[] -> bar1 -> warp0: 8-way sum (+xg) -> DISTANCE-2 xg
//   prefetch (DRAM latency fully hidden; no same-iteration register copy) ->
//   shfl-gather -> pointwise (all 32 lanes, redundant per unit) -> publish
//   tagged words to 8 replicas. Warps 6-7 poll one producer CTA each (8-word
//   tag-batch; single-warp publish makes batch check race-free) -> bar2.
// ---------------------------------------------------------------------------
__device__ __forceinline__ float fsigm(float x) { return 1.0f / (1.0f + __expf(-x)); }
__device__ __forceinline__ float ftanh(float x) { return 2.0f / (1.0f + __expf(-2.0f * x)) - 1.0f; }

__device__ __forceinline__ void lstm_step(
    int tstep, float& xgreg, float& cst,
    float (&hbuf)[2][H_DIM], float* red, const float4 (&wv)[16],
    int tid, int w, int l, int b, int u0, int un, int rowg)
{
    // dot: 64 k-values from smem h (broadcast reads), 4 accumulators
    const float4* hb = reinterpret_cast<const float4*>(&hbuf[tstep & 1][w * 64]);
    float a0 = 0.f, a1 = 0.f, a2 = 0.f, a3 = 0.f;
    #pragma unroll
    for (int i = 0; i < 4; i++) {
        float4 h, q;
        h = hb[i * 4 + 0]; q = wv[i * 4 + 0];
        a0 = fmaf(q.x, h.x, a0); a0 = fmaf(q.y, h.y, a0);
        a0 = fmaf(q.z, h.z, a0); a0 = fmaf(q.w, h.w, a0);
        h = hb[i * 4 + 1]; q = wv[i * 4 + 1];
        a1 = fmaf(q.x, h.x, a1); a1 = fmaf(q.y, h.y, a1);
        a1 = fmaf(q.z, h.z, a1); a1 = fmaf(q.w, h.w, a1);
        h = hb[i * 4 + 2]; q = wv[i * 4 + 2];
        a2 = fmaf(q.x, h.x, a2); a2 = fmaf(q.y, h.y, a2);
        a2 = fmaf(q.z, h.z, a2); a2 = fmaf(q.w, h.w, a2);
        h = hb[i * 4 + 3]; q = wv[i * 4 + 3];
        a3 = fmaf(q.x, h.x, a3); a3 = fmaf(q.y, h.y, a3);
        a3 = fmaf(q.z, h.z, a3); a3 = fmaf(q.w, h.w, a3);
    }
    red[w * 32 + l] = (a0 + a1) + (a2 + a3);
    __syncthreads();   // bar1: red[] complete

    const int par = (tstep + 1) & 1;

    if (tid < 32) {
        // ---- warp 0: reduce + gather + pointwise + publish ----
        float g = xgreg;
        #pragma unroll
        for (int ww = 0; ww < 8; ww++) g += red[ww * 32 + l];
        // distance-2 prefetch: xgreg now dead; reload for step tstep+2.
        // Consumed two iterations from now -> ~2 steps of slack hides DRAM.
        if (tstep + 2 < T_STEPS)
            xgreg = __ldg(&g_xg[(size_t)(tstep + 2) * G4H + rowg]);
        const unsigned FULL = 0xffffffffu;
        const float vi = __shfl_sync(FULL, g, un);
        const float vf = __shfl_sync(FULL, g, 8 + un);
        const float vg = __shfl_sync(FULL, g, 16 + un);
        const float vo = __shfl_sync(FULL, g, 24 + un);
        const float ig = fsigm(vi);
        const float ff = fsigm(vf);
        const float gg = ftanh(vg);
        const float oo = fsigm(vo);
        cst = fmaf(ff, cst, ig * gg);
        const float hn = oo * ftanh(cst);
        const unsigned long long word =
            ((unsigned long long)(unsigned)(tstep + 1) << 32) |
            (unsigned long long)__float_as_uint(hn);
        const int rep = l >> 3;
        unsigned long long* d1 = &g_hx[((size_t)(rep * 2 + par)) * H_DIM + u0 + un];
        unsigned long long* d2 = &g_hx[((size_t)((rep + 4) * 2 + par)) * H_DIM + u0 + un];
        asm volatile("st.global.relaxed.gpu.b64 [%0], %1;" :: "l"(d1), "l"(word) : "memory");
        asm volatile("st.global.relaxed.gpu.b64 [%0], %1;" :: "l"(d2), "l"(word) : "memory");
        if (l < 8) g_hs[(size_t)tstep * H_DIM + u0 + un] = hn;
    } else if (tid >= 192 && tstep + 1 < T_STEPS) {
        // ---- warps 6-7: poller thread j polls producer CTA j (8 units) ----
        const int j    = tid - 192;           // 0..63
        const int crep = b & (NREP - 1);
        const unsigned tgt = (unsigned)(tstep + 1);
        unsigned long long* src =
            &g_hx[((size_t)(crep * 2 + par)) * H_DIM + j * 8];
        unsigned long long v0, v1, v2, v3, v4, v5, v6, v7;
        while (true) {
            asm volatile("ld.global.relaxed.gpu.b64 %0, [%1];" : "=l"(v0) : "l"(src)     : "memory");
            asm volatile("ld.global.relaxed.gpu.b64 %0, [%1];" : "=l"(v1) : "l"(src + 1) : "memory");
            asm volatile("ld.global.relaxed.gpu.b64 %0, [%1];" : "=l"(v2) : "l"(src + 2) : "memory");
            asm volatile("ld.global.relaxed.gpu.b64 %0, [%1];" : "=l"(v3) : "l"(src + 3) : "memory");
            asm volatile("ld.global.relaxed.gpu.b64 %0, [%1];" : "=l"(v4) : "l"(src + 4) : "memory");
            asm volatile("ld.global.relaxed.gpu.b64 %0, [%1];" : "=l"(v5) : "l"(src + 5) : "memory");
            asm volatile("ld.global.relaxed.gpu.b64 %0, [%1];" : "=l"(v6) : "l"(src + 6) : "memory");
            asm volatile("ld.global.relaxed.gpu.b64 %0, [%1];" : "=l"(v7) : "l"(src + 7) : "memory");
            if ((unsigned)(v0 >> 32) == tgt && (unsigned)(v1 >> 32) == tgt &&
                (unsigned)(v2 >> 32) == tgt && (unsigned)(v3 >> 32) == tgt &&
                (unsigned)(v4 >> 32) == tgt && (unsigned)(v5 >> 32) == tgt &&
                (unsigned)(v6 >> 32) == tgt && (unsigned)(v7 >> 32) == tgt)
                break;
        }
        float4 ha, hb2;
        ha.x  = __uint_as_float((unsigned)v0);
        ha.y  = __uint_as_float((unsigned)v1);
        ha.z  = __uint_as_float((unsigned)v2);
        ha.w  = __uint_as_float((unsigned)v3);
        hb2.x = __uint_as_float((unsigned)v4);
        hb2.y = __uint_as_float((unsigned)v5);
        hb2.z = __uint_as_float((unsigned)v6);
        hb2.w = __uint_as_float((unsigned)v7);
        *reinterpret_cast<float4*>(&hbuf[par][j * 8])     = ha;
        *reinterpret_cast<float4*>(&hbuf[par][j * 8 + 4]) = hb2;
    }
    __syncthreads();   // bar2: next-step h ready
}

__global__ void __launch_bounds__(256) lstm_rec(const float* __restrict__ W_hh)
{
    __shared__ float hbuf[2][H_DIM];   // double-buffered h (parity-indexed)
    __shared__ float red[8 * 32];      // per-warp row partials

    const int tid = threadIdx.x;
    const int b   = blockIdx.x;        // 0..63
    const int w   = tid >> 5;
    const int l   = tid & 31;
    const int u0  = b * 8;
    const int un  = l & 7;                         // unit within CTA
    const int rowg = (l >> 3) * H_DIM + u0 + un;   // global gate row (l = row)

    // weights: row rowg, k in [w*64, w*64+64) -> 16 float4 in registers
    float4 wv[16];
    {
        const float4* wp = reinterpret_cast<const float4*>(
            W_hh + (size_t)rowg * H_DIM + (size_t)w * 64);
        #pragma unroll
        for (int i = 0; i < 16; i++) wv[i] = __ldg(wp + i);
    }

    // zero both h buffers (h_0 = 0)
    for (int i = tid; i < 2 * H_DIM; i += 256) (&hbuf[0][0])[i] = 0.f;

    float cst = 0.f;                   // c state (warp 0, per-lane for unit un)
    // xg double-buffer (warp 0): xgA for even steps, xgB for odd steps
    float xgA = 0.f, xgB = 0.f;
    if (w == 0) {
        xgA = __ldg(&g_xg[rowg]);                       // t = 0
        xgB = __ldg(&g_xg[(size_t)G4H + rowg]);         // t = 1
    }
    __syncthreads();

    for (int t = 0; t < T_STEPS; t += 2) {
        lstm_step(t,     xgA, cst, hbuf, red, wv, tid, w, l, b, u0, un, rowg);
        lstm_step(t + 1, xgB, cst, hbuf, red, wv, tid, w, l, b, u0, un, rowg);
    }
}

// ---------------------------------------------------------------------------
// Kernel C: out = log_softmax(hs @ W_out^T + b_out)
// ---------------------------------------------------------------------------
__global__ void __launch_bounds__(256) out_kernel(
    const float* __restrict__ W_out, const float* __restrict__ b_out,
    float* __restrict__ out)
{
    __shared__ float hsm[8 * 512];
    __shared__ float red[256];
    const int tid = threadIdx.x;
    const int t0  = blockIdx.x * 8;

    for (int idx = tid; idx < 8 * 512; idx += 256)
        hsm[idx] = g_hs[(size_t)t0 * H_DIM + idx];
    __syncthreads();

    float acc[8], acc2[8];
    #pragma unroll
    for (int r = 0; r < 8; r++) { acc[r] = 0.f; acc2[r] = 0.f; }

    const float4* wr = reinterpret_cast<const float4*>(W_out + (size_t)tid * H_DIM);
    for (int kk = 0; kk < 128; kk++) {
        const float4 w4 = __ldg(wr + kk);
        #pragma unroll
        for (int rr = 0; rr < 8; rr++) {
            const float4 hv = *reinterpret_cast<const float4*>(&hsm[rr * 512 + kk * 4]);
            float a = acc[rr];
            a = fmaf(w4.x, hv.x, a);
            a = fmaf(w4.y, hv.y, a);
            a = fmaf(w4.z, hv.z, a);
            a = fmaf(w4.w, hv.w, a);
            acc[rr] = a;
        }
    }
    if (tid == 0) {  // column 256
        const float4* wr2 = reinterpret_cast<const float4*>(W_out + (size_t)256 * H_DIM);
        for (int kk = 0; kk < 128; kk++) {
            const float4 w4 = __ldg(wr2 + kk);
            #pragma unroll
            for (int rr = 0; rr < 8; rr++) {
                const float4 hv = *reinterpret_cast<const float4*>(&hsm[rr * 512 + kk * 4]);
                float a = acc2[rr];
                a = fmaf(w4.x, hv.x, a);
                a = fmaf(w4.y, hv.y, a);
                a = fmaf(w4.z, hv.z, a);
                a = fmaf(w4.w, hv.w, a);
                acc2[rr] = a;
            }
        }
    }

    const float bias  = __ldg(b_out + tid);
    const float bias2 = __ldg(b_out + 256);

    for (int r = 0; r < 8; r++) {
        const float z  = acc[r] + bias;
        const float z2 = acc2[r] + bias2;          // meaningful only for tid==0
        float m = (tid == 0) ? fmaxf(z, z2) : z;

        red[tid] = m; __syncthreads();
        for (int s = 128; s > 0; s >>= 1) {
            if (tid < s) red[tid] = fmaxf(red[tid], red[tid + s]);
            __syncthreads();
        }
        const float mx = red[0]; __syncthreads();

        float e = __expf(z - mx);
        if (tid == 0) e += __expf(z2 - mx);
        red[tid] = e; __syncthreads();
        for (int s = 128; s > 0; s >>= 1) {
            if (tid < s) red[tid] += red[tid + s];
            __syncthreads();
        }
        const float lse = logf(red[0]); __syncthreads();

        out[(size_t)(t0 + r) * O_DIM + tid] = z - mx - lse;
        if (tid == 0) out[(size_t)(t0 + r) * O_DIM + 256] = z2 - mx - lse;
    }
}

// ---------------------------------------------------------------------------
// kernel_launch: init -> input GEMM -> recurrence -> output GEMM+softmax
// ---------------------------------------------------------------------------
extern "C" void kernel_launch(void* const* d_in, const int* in_sizes, int n_in,
                              void* d_out, int out_size)
{
    const float* stft  = (const float*)d_in[0];
    const float* W_ih  = (const float*)d_in[1];
    const float* W_hh  = (const float*)d_in[2];
    const float* b_ih  = (const float*)d_in[3];
    const float* b_hh  = (const float*)d_in[4];
    const float* W_out = (const float*)d_in[5];
    const float* b_out = (const float*)d_in[6];
    float* out = (float*)d_out;

    init_kernel<<<8, 256>>>();
    xgate_gemm<<<T_STEPS / 16, 256>>>(stft, W_ih, b_ih, b_hh);
    lstm_rec<<<REC_CTAS, 256>>>(W_hh);
    out_kernel<<<T_STEPS / 8, 256>>>(W_out, b_out, out);
}

// round 13
// speedup vs baseline: 1.0875x; 1.0875x over previous
#include <cuda_runtime.h>
#include <cuda_bf16.h>
#include <math.h>

// Problem constants
#define T_STEPS 16384
#define D_IN    257
#define H_DIM   512
#define G4H     2048   // 4*H
#define O_DIM   257
#define REC_CTAS 64    // recurrence CTAs; each owns 8 hidden units (32 gate rows)
#define NREP    8      // replicas of the h-exchange buffer (spread L2 slices)

// Scratch (static __device__ arrays — no allocation allowed)
__device__ float    g_xg[(size_t)T_STEPS * G4H];   // 128 MB: precomputed input gates + biases
__device__ float    g_hs[(size_t)T_STEPS * H_DIM]; // 32 MB: h per timestep
// Tagged h exchange: [replica][parity][unit] -> (step_tag<<32)|float_bits
__device__ unsigned long long g_hx[NREP * 2 * H_DIM];

// ---------------------------------------------------------------------------
// init: reset exchange tags each launch (tags are monotonic within a launch)
// ---------------------------------------------------------------------------
__global__ void init_kernel() {
    const int idx = blockIdx.x * 256 + threadIdx.x;
    const int n = NREP * 2 * H_DIM;
    for (int i = idx; i < n; i += gridDim.x * 256) g_hx[i] = 0ull;
}

// ---------------------------------------------------------------------------
// Kernel A: x_gates[T, 4H] = stft @ W_ih^T + (b_ih + b_hh)
// ---------------------------------------------------------------------------
__global__ void __launch_bounds__(256) xgate_gemm(
    const float* __restrict__ stft, const float* __restrict__ W_ih,
    const float* __restrict__ b_ih, const float* __restrict__ b_hh)
{
    __shared__ float s_sh[16 * 260];  // row stride 260 (mult of 4 for float4)
    const int tid = threadIdx.x;
    const int t0  = blockIdx.x * 16;

    for (int r = 0; r < 16; r++)
        for (int d = tid; d < D_IN; d += 256)
            s_sh[r * 260 + d] = stft[(size_t)(t0 + r) * D_IN + d];
    __syncthreads();

    for (int cg = 0; cg < 8; cg++) {
        const int c = cg * 256 + tid;                  // 0..2047
        const float* wrow = W_ih + (size_t)c * D_IN;
        float acc[16];
        #pragma unroll
        for (int r = 0; r < 16; r++) acc[r] = 0.f;

        for (int dd = 0; dd < 64; dd++) {              // 64*4 = 256 of 257
            const float w0 = __ldg(wrow + dd * 4 + 0);
            const float w1 = __ldg(wrow + dd * 4 + 1);
            const float w2 = __ldg(wrow + dd * 4 + 2);
            const float w3 = __ldg(wrow + dd * 4 + 3);
            #pragma unroll
            for (int r = 0; r < 16; r++) {
                const float4 s4 = *reinterpret_cast<const float4*>(&s_sh[r * 260 + dd * 4]);
                float a = acc[r];
                a = fmaf(w0, s4.x, a);
                a = fmaf(w1, s4.y, a);
                a = fmaf(w2, s4.z, a);
                a = fmaf(w3, s4.w, a);
                acc[r] = a;
            }
        }
        const float wl = __ldg(wrow + 256);            // remainder d = 256
        #pragma unroll
        for (int r = 0; r < 16; r++) acc[r] = fmaf(wl, s_sh[r * 260 + 256], acc[r]);

        const float bias = __ldg(b_ih + c) + __ldg(b_hh + c);
        #pragma unroll
        for (int r = 0; r < 16; r++)
            g_xg[(size_t)(t0 + r) * G4H + c] = acc[r] + bias;
    }
}

// ---------------------------------------------------------------------------
// Kernel B: LSTM recurrence, persistent 64 CTAs x 256 threads, SELF-POLLING
// warps. CTA b owns units u0=8b..8b+7 (32 gate rows). Warp w, lane l:
//   row = l (gate=l>>3, unit=l&7), k-segment = [64w, 64w+64).
// Each warp polls ITS OWN 64 tagged h-words (2 b64 loads/lane), writes its
// private smem segment, __syncwarp, dot, red[par] -> single __syncthreads ->
// warp 0: 8-way sum + xg + shfl-gather + pointwise + publish to 8 replicas.
// No second barrier: red[] is parity double-buffered; all cross-step reuse
// is ordered through the tag-catch dependency chain.
// ---------------------------------------------------------------------------
__device__ __forceinline__ float fsigm(float x) { return 1.0f / (1.0f + __expf(-x)); }
__device__ __forceinline__ float ftanh(float x) { return 2.0f / (1.0f + __expf(-2.0f * x)) - 1.0f; }

__device__ __forceinline__ void lstm_step(
    int tstep, float& xgreg, float& cst,
    float (&hseg)[8][64], float (&red)[2][256], const float4 (&wv)[16],
    int tid, int w, int l, int u0, int un, int rowg, int crep)
{
    // ---- poll own k-segment: tag == tstep (h produced at iter tstep-1) ----
    if (tstep > 0) {
        const unsigned tgt = (unsigned)tstep;
        const int par = tstep & 1;
        unsigned long long* src =
            &g_hx[((size_t)(crep * 2 + par)) * H_DIM + w * 64 + 2 * l];
        unsigned long long v0, v1;
        while (true) {
            asm volatile("ld.global.relaxed.gpu.b64 %0, [%1];" : "=l"(v0) : "l"(src)     : "memory");
            asm volatile("ld.global.relaxed.gpu.b64 %0, [%1];" : "=l"(v1) : "l"(src + 1) : "memory");
            if ((unsigned)(v0 >> 32) == tgt && (unsigned)(v1 >> 32) == tgt) break;
        }
        hseg[w][2 * l]     = __uint_as_float((unsigned)v0);
        hseg[w][2 * l + 1] = __uint_as_float((unsigned)v1);
        __syncwarp();
    }

    // ---- dot: 64 k-values from own smem segment (broadcast reads) ----
    const float4* hb = reinterpret_cast<const float4*>(&hseg[w][0]);
    float a0 = 0.f, a1 = 0.f, a2 = 0.f, a3 = 0.f;
    #pragma unroll
    for (int i = 0; i < 4; i++) {
        float4 h, q;
        h = hb[i * 4 + 0]; q = wv[i * 4 + 0];
        a0 = fmaf(q.x, h.x, a0); a0 = fmaf(q.y, h.y, a0);
        a0 = fmaf(q.z, h.z, a0); a0 = fmaf(q.w, h.w, a0);
        h = hb[i * 4 + 1]; q = wv[i * 4 + 1];
        a1 = fmaf(q.x, h.x, a1); a1 = fmaf(q.y, h.y, a1);
        a1 = fmaf(q.z, h.z, a1); a1 = fmaf(q.w, h.w, a1);
        h = hb[i * 4 + 2]; q = wv[i * 4 + 2];
        a2 = fmaf(q.x, h.x, a2); a2 = fmaf(q.y, h.y, a2);
        a2 = fmaf(q.z, h.z, a2); a2 = fmaf(q.w, h.w, a2);
        h = hb[i * 4 + 3]; q = wv[i * 4 + 3];
        a3 = fmaf(q.x, h.x, a3); a3 = fmaf(q.y, h.y, a3);
        a3 = fmaf(q.z, h.z, a3); a3 = fmaf(q.w, h.w, a3);
    }
    red[tstep & 1][w * 32 + l] = (a0 + a1) + (a2 + a3);
    __syncthreads();   // the single barrier: red[] complete

    if (tid < 32) {
        // ---- warp 0: reduce + gather + pointwise + publish ----
        const float* rp = &red[tstep & 1][0];
        float g = xgreg;
        #pragma unroll
        for (int ww = 0; ww < 8; ww++) g += rp[ww * 32 + l];
        // distance-2 xg prefetch (register now dead, consumed 2 iters later)
        if (tstep + 2 < T_STEPS)
            xgreg = __ldg(&g_xg[(size_t)(tstep + 2) * G4H + rowg]);
        const unsigned FULL = 0xffffffffu;
        const float vi = __shfl_sync(FULL, g, un);
        const float vf = __shfl_sync(FULL, g, 8 + un);
        const float vg = __shfl_sync(FULL, g, 16 + un);
        const float vo = __shfl_sync(FULL, g, 24 + un);
        const float ig = fsigm(vi);
        const float ff = fsigm(vf);
        const float gg = ftanh(vg);
        const float oo = fsigm(vo);
        cst = fmaf(ff, cst, ig * gg);
        const float hn = oo * ftanh(cst);
        const int par2 = (tstep + 1) & 1;
        const unsigned long long word =
            ((unsigned long long)(unsigned)(tstep + 1) << 32) |
            (unsigned long long)__float_as_uint(hn);
        const int rep = l >> 3;
        unsigned long long* d1 = &g_hx[((size_t)(rep * 2 + par2)) * H_DIM + u0 + un];
        unsigned long long* d2 = &g_hx[((size_t)((rep + 4) * 2 + par2)) * H_DIM + u0 + un];
        asm volatile("st.global.relaxed.gpu.b64 [%0], %1;" :: "l"(d1), "l"(word) : "memory");
        asm volatile("st.global.relaxed.gpu.b64 [%0], %1;" :: "l"(d2), "l"(word) : "memory");
        if (l < 8) g_hs[(size_t)tstep * H_DIM + u0 + un] = hn;
    }
}

__global__ void __launch_bounds__(256) lstm_rec(const float* __restrict__ W_hh)
{
    __shared__ float hseg[8][64];      // per-warp h segment (self-polled)
    __shared__ float red[2][256];      // parity double-buffered row partials

    const int tid = threadIdx.x;
    const int b   = blockIdx.x;        // 0..63
    const int w   = tid >> 5;
    const int l   = tid & 31;
    const int u0  = b * 8;
    const int un  = l & 7;                         // unit within CTA
    const int rowg = (l >> 3) * H_DIM + u0 + un;   // global gate row (l = row)
    const int crep = b & (NREP - 1);               // replica this CTA polls

    // weights: row rowg, k in [w*64, w*64+64) -> 16 float4 in registers
    float4 wv[16];
    {
        const float4* wp = reinterpret_cast<const float4*>(
            W_hh + (size_t)rowg * H_DIM + (size_t)w * 64);
        #pragma unroll
        for (int i = 0; i < 16; i++) wv[i] = __ldg(wp + i);
    }

    // zero h segments (h_0 = 0)
    for (int i = tid; i < 8 * 64; i += 256) (&hseg[0][0])[i] = 0.f;

    float cst = 0.f;                   // c state (warp 0, per-lane for unit un)
    // xg double-buffer (warp 0): xgA for even steps, xgB for odd steps
    float xgA = 0.f, xgB = 0.f;
    if (w == 0) {
        xgA = __ldg(&g_xg[rowg]);                       // t = 0
        xgB = __ldg(&g_xg[(size_t)G4H + rowg]);         // t = 1
    }
    __syncthreads();

    for (int t = 0; t < T_STEPS; t += 2) {
        lstm_step(t,     xgA, cst, hseg, red, wv, tid, w, l, u0, un, rowg, crep);
        lstm_step(t + 1, xgB, cst, hseg, red, wv, tid, w, l, u0, un, rowg, crep);
    }
}

// ---------------------------------------------------------------------------
// Kernel C: out = log_softmax(hs @ W_out^T + b_out)
// ---------------------------------------------------------------------------
__global__ void __launch_bounds__(256) out_kernel(
    const float* __restrict__ W_out, const float* __restrict__ b_out,
    float* __restrict__ out)
{
    __shared__ float hsm[8 * 512];
    __shared__ float red[256];
    const int tid = threadIdx.x;
    const int t0  = blockIdx.x * 8;

    for (int idx = tid; idx < 8 * 512; idx += 256)
        hsm[idx] = g_hs[(size_t)t0 * H_DIM + idx];
    __syncthreads();

    float acc[8], acc2[8];
    #pragma unroll
    for (int r = 0; r < 8; r++) { acc[r] = 0.f; acc2[r] = 0.f; }

    const float4* wr = reinterpret_cast<const float4*>(W_out + (size_t)tid * H_DIM);
    for (int kk = 0; kk < 128; kk++) {
        const float4 w4 = __ldg(wr + kk);
        #pragma unroll
        for (int rr = 0; rr < 8; rr++) {
            const float4 hv = *reinterpret_cast<const float4*>(&hsm[rr * 512 + kk * 4]);
            float a = acc[rr];
            a = fmaf(w4.x, hv.x, a);
            a = fmaf(w4.y, hv.y, a);
            a = fmaf(w4.z, hv.z, a);
            a = fmaf(w4.w, hv.w, a);
            acc[rr] = a;
        }
    }
    if (tid == 0) {  // column 256
        const float4* wr2 = reinterpret_cast<const float4*>(W_out + (size_t)256 * H_DIM);
        for (int kk = 0; kk < 128; kk++) {
            const float4 w4 = __ldg(wr2 + kk);
            #pragma unroll
            for (int rr = 0; rr < 8; rr++) {
                const float4 hv = *reinterpret_cast<const float4*>(&hsm[rr * 512 + kk * 4]);
                float a = acc2[rr];
                a = fmaf(w4.x, hv.x, a);
                a = fmaf(w4.y, hv.y, a);
                a = fmaf(w4.z, hv.z, a);
                a = fmaf(w4.w, hv.w, a);
                acc2[rr] = a;
            }
        }
    }

    const float bias  = __ldg(b_out + tid);
    const float bias2 = __ldg(b_out + 256);

    for (int r = 0; r < 8; r++) {
        const float z  = acc[r] + bias;
        const float z2 = acc2[r] + bias2;          // meaningful only for tid==0
        float m = (tid == 0) ? fmaxf(z, z2) : z;

        red[tid] = m; __syncthreads();
        for (int s = 128; s > 0; s >>= 1) {
            if (tid < s) red[tid] = fmaxf(red[tid], red[tid + s]);
            __syncthreads();
        }
        const float mx = red[0]; __syncthreads();

        float e = __expf(z - mx);
        if (tid == 0) e += __expf(z2 - mx);
        red[tid] = e; __syncthreads();
        for (int s = 128; s > 0; s >>= 1) {
            if (tid < s) red[tid] += red[tid + s];
            __syncthreads();
        }
        const float lse = logf(red[0]); __syncthreads();

        out[(size_t)(t0 + r) * O_DIM + tid] = z - mx - lse;
        if (tid == 0) out[(size_t)(t0 + r) * O_DIM + 256] = z2 - mx - lse;
    }
}

// ---------------------------------------------------------------------------
// kernel_launch: init -> input GEMM -> recurrence -> output GEMM+softmax
// ---------------------------------------------------------------------------
extern "C" void kernel_launch(void* const* d_in, const int* in_sizes, int n_in,
                              void* d_out, int out_size)
{
    const float* stft  = (const float*)d_in[0];
    const float* W_ih  = (const float*)d_in[1];
    const float* W_hh  = (const float*)d_in[2];
    const float* b_ih  = (const float*)d_in[3];
    const float* b_hh  = (const float*)d_in[4];
    const float* W_out = (const float*)d_in[5];
    const float* b_out = (const float*)d_in[6];
    float* out = (float*)d_out;

    init_kernel<<<8, 256>>>();
    xgate_gemm<<<T_STEPS / 16, 256>>>(stft, W_ih, b_ih, b_hh);
    lstm_rec<<<REC_CTAS, 256>>>(W_hh);
    out_kernel<<<T_STEPS / 8, 256>>>(W_out, b_out, out);
}